// round 3
// baseline (speedup 1.0000x reference)
#include <cuda_runtime.h>

#define NMAX 100000
#define EMAX 1600000
#define FIN  128
#define HID  48
#define NC   40
#define CAT  144
#define EPSB 1e-5f
#define SLOPE 0.01f

// ---------------- device scratch (static, allocation-free) ----------------
__device__ __align__(16) float  g_y[NMAX * HID];      // y (pre-BN, post-lrelu) per layer
__device__ __align__(16) float  g_hw[NMAX * HID];     // h @ Wc (BN-folded)
__device__ __align__(16) float  g_cat[NMAX * CAT];    // [h1 | h2 | y3(raw)]
__device__ float  g_deg[NMAX];
__device__ float  g_dinv[NMAX];
__device__ int    g_cnt[NMAX];
__device__ int    g_rowptr[NMAX + 1];
__device__ int    g_wp[NMAX];
__device__ int    g_bsum[256];
__device__ __align__(16) float2 g_ec[EMAX];           // {coef, src-as-float-bits}
__device__ float  g_part[128 * 2 * HID];              // stats partials
__device__ float  g_scale[HID], g_shift[HID];         // BN affine a, c
__device__ float  g_wfold[HID * HID], g_bfold[HID];
__device__ float  g_wout[CAT * NC], g_bout[NC];

__device__ __forceinline__ float lrelu(float v) { return v >= 0.f ? v : SLOPE * v; }

// ---------------- graph-structure kernels ----------------
__global__ void k_zero(int N) {
    int i = blockIdx.x * blockDim.x + threadIdx.x;
    if (i < N) { g_deg[i] = 0.f; g_cnt[i] = 0; }
}

__global__ void k_degcnt(const int* __restrict__ ei, const float* __restrict__ ew, int E) {
    int e = blockIdx.x * blockDim.x + threadIdx.x;
    if (e >= E) return;
    int dst = ei[E + e];
    atomicAdd(&g_deg[dst], ew[e]);
    atomicAdd(&g_cnt[dst], 1);
}

__global__ void k_dinv(int N) {
    int i = blockIdx.x * blockDim.x + threadIdx.x;
    if (i < N) g_dinv[i] = rsqrtf(g_deg[i] + 1.0f);   // +1 = self loop weight
}

__global__ void k_scanA(int N) {
    __shared__ int s[1024];
    int tid = threadIdx.x;
    int i = blockIdx.x * 1024 + tid;
    int v = (i < N) ? g_cnt[i] : 0;
    s[tid] = v;
    __syncthreads();
    for (int off = 1; off < 1024; off <<= 1) {
        int t = (tid >= off) ? s[tid - off] : 0;
        __syncthreads();
        s[tid] += t;
        __syncthreads();
    }
    if (i < N) g_rowptr[i] = s[tid] - v;       // exclusive within block
    if (tid == 1023) g_bsum[blockIdx.x] = s[1023];
}

__global__ void k_scanB(int SB, int N) {
    int run = 0;
    for (int b = 0; b < SB; ++b) { int t = g_bsum[b]; g_bsum[b] = run; run += t; }
    g_rowptr[N] = run;
}

__global__ void k_scanC(int N) {
    int i = blockIdx.x * blockDim.x + threadIdx.x;
    if (i < N) {
        int v = g_rowptr[i] + g_bsum[i >> 10];
        g_rowptr[i] = v;
        g_wp[i] = v;
    }
}

__global__ void k_fill(const int* __restrict__ ei, const float* __restrict__ ew, int E) {
    int e = blockIdx.x * blockDim.x + threadIdx.x;
    if (e >= E) return;
    int src = ei[e];
    int dst = ei[E + e];
    int pos = atomicAdd(&g_wp[dst], 1);
    float coef = g_dinv[src] * ew[e] * g_dinv[dst];
    g_ec[pos] = make_float2(coef, __int_as_float(src));
}

// ---------------- GEMM 1: g_y = lrelu(x @ W_first + b) ----------------
__global__ __launch_bounds__(128) void k_gemm1(const float* __restrict__ A,
                                               const float* __restrict__ W,
                                               const float* __restrict__ bias, int N) {
    __shared__ float As[128][33];
    __shared__ float Ws[32][48];
    int tid = threadIdx.x;
    int ty = tid >> 3, tx = tid & 7;          // 16 x 8
    int base = blockIdx.x * 128;
    float acc[8][6];
#pragma unroll
    for (int r = 0; r < 8; ++r)
#pragma unroll
        for (int c = 0; c < 6; ++c) acc[r][c] = 0.f;

#pragma unroll 1
    for (int k0 = 0; k0 < FIN; k0 += 32) {
#pragma unroll
        for (int t = 0; t < 8; ++t) {
            int idx = tid + t * 128;          // 0..1023 float4
            int r = idx >> 3, q = idx & 7;
            float4 v = make_float4(0.f, 0.f, 0.f, 0.f);
            int gr = base + r;
            if (gr < N) v = *(const float4*)(A + (size_t)gr * FIN + k0 + q * 4);
            As[r][q * 4 + 0] = v.x; As[r][q * 4 + 1] = v.y;
            As[r][q * 4 + 2] = v.z; As[r][q * 4 + 3] = v.w;
        }
#pragma unroll
        for (int t = 0; t < 12; ++t) {
            int idx = tid + t * 128;          // 0..1535
            int k = idx / 48, j = idx % 48;
            Ws[k][j] = W[(k0 + k) * 48 + j];
        }
        __syncthreads();
#pragma unroll 8
        for (int kk = 0; kk < 32; ++kk) {
            float a[8], w[6];
#pragma unroll
            for (int r = 0; r < 8; ++r) a[r] = As[ty * 8 + r][kk];
#pragma unroll
            for (int c = 0; c < 6; ++c) w[c] = Ws[kk][tx * 6 + c];
#pragma unroll
            for (int r = 0; r < 8; ++r)
#pragma unroll
                for (int c = 0; c < 6; ++c) acc[r][c] += a[r] * w[c];
        }
        __syncthreads();
    }
#pragma unroll
    for (int r = 0; r < 8; ++r) {
        int gr = base + ty * 8 + r;
        if (gr >= N) continue;
#pragma unroll
        for (int c = 0; c < 6; ++c) {
            int j = tx * 6 + c;
            g_y[(size_t)gr * HID + j] = lrelu(acc[r][c] + bias[j]);
        }
    }
}

// ---------------- GEMM H: g_hw = y @ Wfold + bfold; g_cat <- a*y+c ----------------
__global__ __launch_bounds__(128) void k_gemm_h(int colOff, int N) {
    const float* __restrict__ Y = g_y;
    __shared__ float As[128][49];
    __shared__ float Ws[48][48];
    int tid = threadIdx.x;
    int ty = tid >> 3, tx = tid & 7;
    int base = blockIdx.x * 128;
    float acc[8][6];
#pragma unroll
    for (int r = 0; r < 8; ++r)
#pragma unroll
        for (int c = 0; c < 6; ++c) acc[r][c] = 0.f;

#pragma unroll
    for (int t = 0; t < 12; ++t) {
        int idx = tid + t * 128;              // 0..1535 float4
        int r = idx / 12, q = idx % 12;
        float4 v = make_float4(0.f, 0.f, 0.f, 0.f);
        int gr = base + r;
        if (gr < N) v = *(const float4*)(Y + (size_t)gr * HID + q * 4);
        int j = q * 4;
        As[r][j + 0] = v.x; As[r][j + 1] = v.y; As[r][j + 2] = v.z; As[r][j + 3] = v.w;
        if (gr < N) {
            float* dst = g_cat + (size_t)gr * CAT + colOff + j;
            dst[0] = g_scale[j + 0] * v.x + g_shift[j + 0];
            dst[1] = g_scale[j + 1] * v.y + g_shift[j + 1];
            dst[2] = g_scale[j + 2] * v.z + g_shift[j + 2];
            dst[3] = g_scale[j + 3] * v.w + g_shift[j + 3];
        }
    }
#pragma unroll
    for (int t = 0; t < 18; ++t) {
        int idx = tid + t * 128;              // 0..2303
        Ws[idx / 48][idx % 48] = g_wfold[idx];
    }
    __syncthreads();
#pragma unroll 8
    for (int kk = 0; kk < 48; ++kk) {
        float a[8], w[6];
#pragma unroll
        for (int r = 0; r < 8; ++r) a[r] = As[ty * 8 + r][kk];
#pragma unroll
        for (int c = 0; c < 6; ++c) w[c] = Ws[kk][tx * 6 + c];
#pragma unroll
        for (int r = 0; r < 8; ++r)
#pragma unroll
            for (int c = 0; c < 6; ++c) acc[r][c] += a[r] * w[c];
    }
#pragma unroll
    for (int r = 0; r < 8; ++r) {
        int gr = base + ty * 8 + r;
        if (gr >= N) continue;
#pragma unroll
        for (int c = 0; c < 6; ++c) {
            int j = tx * 6 + c;
            g_hw[(size_t)gr * HID + j] = acc[r][c] + g_bfold[j];
        }
    }
}

// ---------------- stats (deterministic 2-level column mean/var) ----------------
__global__ void k_stats1(int sel, int N) {
    const float* __restrict__ Y = (sel == 0) ? g_y : (g_cat + 96);
    int ld = (sel == 0) ? HID : CAT;
    int col = threadIdx.x % 48, rs = threadIdx.x / 48;    // blockDim 384
    float s = 0.f, q = 0.f;
    for (int r = blockIdx.x * 8 + rs; r < N; r += 128 * 8) {
        float v = Y[(size_t)r * ld + col];
        s += v; q += v * v;
    }
    __shared__ float sh[384], shq[384];
    sh[threadIdx.x] = s; shq[threadIdx.x] = q;
    __syncthreads();
    if (threadIdx.x < 48) {
#pragma unroll
        for (int i = 1; i < 8; ++i) { s += sh[i * 48 + col]; q += shq[i * 48 + col]; }
        g_part[blockIdx.x * 96 + col] = s;
        g_part[blockIdx.x * 96 + 48 + col] = q;
    }
}

__global__ void k_stats2(const float* __restrict__ g, const float* __restrict__ b, float invN) {
    int j = threadIdx.x;
    if (j >= 48) return;
    float s = 0.f, q = 0.f;
    for (int blk = 0; blk < 128; ++blk) { s += g_part[blk * 96 + j]; q += g_part[blk * 96 + 48 + j]; }
    float mean = s * invN;
    float var = q * invN - mean * mean;
    float a = g[j] * rsqrtf(var + EPSB);
    g_scale[j] = a;
    g_shift[j] = b[j] - mean * a;
}

__global__ void k_fold(const float* __restrict__ Wc) {
    for (int idx = threadIdx.x; idx < HID * HID; idx += blockDim.x)
        g_wfold[idx] = g_scale[idx / HID] * Wc[idx];
    if (threadIdx.x < HID) {
        float s = 0.f;
        for (int k = 0; k < HID; ++k) s += g_shift[k] * Wc[k * HID + threadIdx.x];
        g_bfold[threadIdx.x] = s;
    }
}

__global__ void k_fold_out(const float* __restrict__ Wout, const float* __restrict__ bout) {
    for (int idx = threadIdx.x; idx < CAT * NC; idx += blockDim.x) {
        int k = idx / NC;
        g_wout[idx] = (k < 96) ? Wout[idx] : g_scale[k - 96] * Wout[idx];
    }
    if (threadIdx.x < NC) {
        float s = bout[threadIdx.x];
        for (int k = 0; k < HID; ++k) s += g_shift[k] * Wout[(96 + k) * NC + threadIdx.x];
        g_bout[threadIdx.x] = s;
    }
}

// ---------------- sparse conv (gather, CSR by dst) ----------------
__global__ void k_conv(const float* __restrict__ bias, int outSel, int N) {
    float* __restrict__ out = (outSel == 0) ? g_y : (g_cat + 96);
    int ld = (outSel == 0) ? HID : CAT;
    int g = blockIdx.x * blockDim.x + threadIdx.x;
    int node = g >> 2;
    if (node >= N) return;
    int sub = g & 3;                          // 12 floats each
    float di = g_dinv[node];
    float s = di * di;                        // self-loop norm
    const float4* hs = (const float4*)(g_hw + (size_t)node * HID + sub * 12);
    float4 a0 = hs[0], a1 = hs[1], a2 = hs[2];
    float4 c0 = make_float4(s * a0.x, s * a0.y, s * a0.z, s * a0.w);
    float4 c1 = make_float4(s * a1.x, s * a1.y, s * a1.z, s * a1.w);
    float4 c2 = make_float4(s * a2.x, s * a2.y, s * a2.z, s * a2.w);
    int beg = g_rowptr[node], end = g_rowptr[node + 1];
    for (int j = beg; j < end; ++j) {
        float2 e = g_ec[j];
        int src = __float_as_int(e.y);
        float cf = e.x;
        const float4* p = (const float4*)(g_hw + (size_t)src * HID + sub * 12);
        float4 v0 = p[0], v1 = p[1], v2 = p[2];
        c0.x += cf * v0.x; c0.y += cf * v0.y; c0.z += cf * v0.z; c0.w += cf * v0.w;
        c1.x += cf * v1.x; c1.y += cf * v1.y; c1.z += cf * v1.z; c1.w += cf * v1.w;
        c2.x += cf * v2.x; c2.y += cf * v2.y; c2.z += cf * v2.z; c2.w += cf * v2.w;
    }
    int cb = sub * 12;
    const float4* bp = (const float4*)(bias + cb);
    float4 b0 = bp[0], b1 = bp[1], b2 = bp[2];
    float4 o0 = make_float4(lrelu(c0.x + b0.x), lrelu(c0.y + b0.y), lrelu(c0.z + b0.z), lrelu(c0.w + b0.w));
    float4 o1 = make_float4(lrelu(c1.x + b1.x), lrelu(c1.y + b1.y), lrelu(c1.z + b1.z), lrelu(c1.w + b1.w));
    float4 o2 = make_float4(lrelu(c2.x + b2.x), lrelu(c2.y + b2.y), lrelu(c2.z + b2.z), lrelu(c2.w + b2.w));
    float4* op = (float4*)(out + (size_t)node * ld + cb);
    op[0] = o0; op[1] = o1; op[2] = o2;
}

// ---------------- head GEMM + log_softmax ----------------
__global__ __launch_bounds__(128) void k_gemm_out(float* __restrict__ out, int N) {
    __shared__ float As[128][49];
    __shared__ float Ws[48][40];
    int tid = threadIdx.x;
    int ty = tid >> 3, tx = tid & 7;          // 16 x 8; 8 rows x 5 cols per thread
    int base = blockIdx.x * 128;
    float acc[8][5];
#pragma unroll
    for (int r = 0; r < 8; ++r)
#pragma unroll
        for (int c = 0; c < 5; ++c) acc[r][c] = 0.f;

#pragma unroll 1
    for (int k0 = 0; k0 < CAT; k0 += 48) {
#pragma unroll
        for (int t = 0; t < 12; ++t) {
            int idx = tid + t * 128;          // float4
            int r = idx / 12, q = idx % 12;
            float4 v = make_float4(0.f, 0.f, 0.f, 0.f);
            int gr = base + r;
            if (gr < N) v = *(const float4*)(g_cat + (size_t)gr * CAT + k0 + q * 4);
            int j = q * 4;
            As[r][j + 0] = v.x; As[r][j + 1] = v.y; As[r][j + 2] = v.z; As[r][j + 3] = v.w;
        }
#pragma unroll
        for (int t = 0; t < 15; ++t) {
            int idx = tid + t * 128;          // 0..1919
            Ws[idx / 40][idx % 40] = g_wout[k0 * 40 + idx];
        }
        __syncthreads();
#pragma unroll 8
        for (int kk = 0; kk < 48; ++kk) {
            float a[8], w[5];
#pragma unroll
            for (int r = 0; r < 8; ++r) a[r] = As[ty * 8 + r][kk];
#pragma unroll
            for (int c = 0; c < 5; ++c) w[c] = Ws[kk][tx * 5 + c];
#pragma unroll
            for (int r = 0; r < 8; ++r)
#pragma unroll
                for (int c = 0; c < 5; ++c) acc[r][c] += a[r] * w[c];
        }
        __syncthreads();
    }
    // log_softmax over 40 cols: 8-lane groups (tx 0..7) hold one row
#pragma unroll
    for (int r = 0; r < 8; ++r) {
        int gr = base + ty * 8 + r;
        float v[5];
        float m = -1e30f;
#pragma unroll
        for (int c = 0; c < 5; ++c) { v[c] = acc[r][c] + g_bout[tx * 5 + c]; m = fmaxf(m, v[c]); }
#pragma unroll
        for (int off = 1; off < 8; off <<= 1) m = fmaxf(m, __shfl_xor_sync(0xffffffffu, m, off));
        float se = 0.f;
#pragma unroll
        for (int c = 0; c < 5; ++c) se += __expf(v[c] - m);
#pragma unroll
        for (int off = 1; off < 8; off <<= 1) se += __shfl_xor_sync(0xffffffffu, se, off);
        float ls = __logf(se);
        if (gr < N) {
#pragma unroll
            for (int c = 0; c < 5; ++c) out[(size_t)gr * NC + tx * 5 + c] = v[c] - m - ls;
        }
    }
}

// ---------------- launch ----------------
extern "C" void kernel_launch(void* const* d_in, const int* in_sizes, int n_in,
                              void* d_out, int out_size) {
    const float* x    = (const float*)d_in[0];
    const int*   ei   = (const int*)d_in[1];     // int32! (JAX demotes int64 without x64)
    const float* ew   = (const float*)d_in[2];
    const float* Wf   = (const float*)d_in[3];
    const float* bf   = (const float*)d_in[4];
    const float* bn1g = (const float*)d_in[5];
    const float* bn1b = (const float*)d_in[6];
    const float* Wc1  = (const float*)d_in[7];
    const float* bc1  = (const float*)d_in[8];
    const float* bn2g = (const float*)d_in[9];
    const float* bn2b = (const float*)d_in[10];
    const float* Wc2  = (const float*)d_in[11];
    const float* bc2  = (const float*)d_in[12];
    const float* bn3g = (const float*)d_in[13];
    const float* bn3b = (const float*)d_in[14];
    const float* Wout = (const float*)d_in[15];
    const float* bout = (const float*)d_in[16];
    float* out = (float*)d_out;

    int N = in_sizes[0] / FIN;
    int E = in_sizes[2];
    float invN = 1.0f / (float)N;
    int SB = (N + 1023) / 1024;
    int gN = (N + 255) / 256;
    int gE = (E + 255) / 256;
    int gT = (N + 127) / 128;       // gemm row blocks
    int gC = (4 * N + 255) / 256;   // conv

    // graph structure
    k_zero<<<gN, 256>>>(N);
    k_degcnt<<<gE, 256>>>(ei, ew, E);
    k_dinv<<<gN, 256>>>(N);
    k_scanA<<<SB, 1024>>>(N);
    k_scanB<<<1, 1>>>(SB, N);
    k_scanC<<<gN, 256>>>(N);
    k_fill<<<gE, 256>>>(ei, ew, E);

    // layer 1
    k_gemm1<<<gT, 128>>>(x, Wf, bf, N);
    k_stats1<<<128, 384>>>(0, N);
    k_stats2<<<1, 64>>>(bn1g, bn1b, invN);
    k_fold<<<1, 256>>>(Wc1);
    k_gemm_h<<<gT, 128>>>(0, N);
    k_conv<<<gC, 256>>>(bc1, 0, N);

    // layer 2
    k_stats1<<<128, 384>>>(0, N);
    k_stats2<<<1, 64>>>(bn2g, bn2b, invN);
    k_fold<<<1, 256>>>(Wc2);
    k_gemm_h<<<gT, 128>>>(HID, N);
    k_conv<<<gC, 256>>>(bc2, 1, N);

    // layer 3 stats folded into output weights
    k_stats1<<<128, 384>>>(1, N);
    k_stats2<<<1, 64>>>(bn3g, bn3b, invN);
    k_fold_out<<<1, 256>>>(Wout, bout);

    k_gemm_out<<<gT, 128>>>(out, N);
}

// round 4
// speedup vs baseline: 1.0488x; 1.0488x over previous
#include <cuda_runtime.h>

#define NMAX 100000
#define EMAX 1600000
#define FIN  128
#define HID  48
#define NC   40
#define CAT  144
#define EPSB 1e-5f
#define SLOPE 0.01f

// ---------------- device scratch (static, allocation-free) ----------------
__device__ __align__(16) float  g_y[NMAX * HID];      // y (pre-BN, post-lrelu) per layer
__device__ __align__(16) float  g_hw[NMAX * HID];     // h @ Wc (BN-folded)
__device__ __align__(16) float  g_cat[NMAX * CAT];    // [h1 | h2 | y3(raw)]
__device__ float  g_deg[NMAX];
__device__ float  g_dinv[NMAX];
__device__ int    g_cnt[NMAX];
__device__ int    g_rowptr[NMAX + 1];
__device__ int    g_wp[NMAX];
__device__ int    g_bsum[256];
__device__ __align__(16) float2 g_ec[EMAX];           // {coef, src-as-float-bits}
__device__ float  g_part[128 * 2 * HID];              // stats partials
__device__ float  g_scale[HID], g_shift[HID];         // BN affine a, c
__device__ float  g_wfold[HID * HID], g_bfold[HID];
__device__ float  g_wout[CAT * NC], g_bout[NC];

__device__ __forceinline__ float lrelu(float v) { return v >= 0.f ? v : SLOPE * v; }

// ---- packed f32x2 helpers (FFMA2 only reachable via PTX) ----
__device__ __forceinline__ unsigned long long fma2(unsigned long long a,
                                                   unsigned long long b,
                                                   unsigned long long c) {
    unsigned long long d;
    asm("fma.rn.f32x2 %0, %1, %2, %3;" : "=l"(d) : "l"(a), "l"(b), "l"(c));
    return d;
}
__device__ __forceinline__ unsigned long long pack2(float lo, float hi) {
    unsigned long long r;
    asm("mov.b64 %0, {%1, %2};" : "=l"(r) : "f"(lo), "f"(hi));
    return r;
}
__device__ __forceinline__ void unpack2(unsigned long long v, float& lo, float& hi) {
    asm("mov.b64 {%0, %1}, %2;" : "=f"(lo), "=f"(hi) : "l"(v));
}

// ---------------- graph-structure kernels ----------------
__global__ void k_zero(int N) {
    int i = blockIdx.x * blockDim.x + threadIdx.x;
    if (i < N) { g_deg[i] = 0.f; g_cnt[i] = 0; }
}

__global__ void k_degcnt(const int* __restrict__ ei, const float* __restrict__ ew, int E) {
    int e = blockIdx.x * blockDim.x + threadIdx.x;
    if (e >= E) return;
    int dst = ei[E + e];
    atomicAdd(&g_deg[dst], ew[e]);
    atomicAdd(&g_cnt[dst], 1);
}

// block scan over counts (+ fused dinv)
__global__ void k_scanA(int N) {
    __shared__ int s[1024];
    int tid = threadIdx.x;
    int i = blockIdx.x * 1024 + tid;
    int v = (i < N) ? g_cnt[i] : 0;
    if (i < N) g_dinv[i] = rsqrtf(g_deg[i] + 1.0f);   // +1 = self-loop weight
    s[tid] = v;
    __syncthreads();
    for (int off = 1; off < 1024; off <<= 1) {
        int t = (tid >= off) ? s[tid - off] : 0;
        __syncthreads();
        s[tid] += t;
        __syncthreads();
    }
    if (i < N) g_rowptr[i] = s[tid] - v;       // exclusive within block
    if (tid == 1023) g_bsum[blockIdx.x] = s[1023];
}

__global__ void k_scanB(int SB, int N) {
    int run = 0;
    for (int b = 0; b < SB; ++b) { int t = g_bsum[b]; g_bsum[b] = run; run += t; }
    g_rowptr[N] = run;
}

__global__ void k_scanC(int N) {
    int i = blockIdx.x * blockDim.x + threadIdx.x;
    if (i < N) {
        int v = g_rowptr[i] + g_bsum[i >> 10];
        g_rowptr[i] = v;
        g_wp[i] = v;
    }
}

__global__ void k_fill(const int* __restrict__ ei, const float* __restrict__ ew, int E) {
    int e = blockIdx.x * blockDim.x + threadIdx.x;
    if (e >= E) return;
    int src = ei[e];
    int dst = ei[E + e];
    int pos = atomicAdd(&g_wp[dst], 1);
    float coef = g_dinv[src] * ew[e] * g_dinv[dst];
    g_ec[pos] = make_float2(coef, __int_as_float(src));
}

// ---------------- GEMM 1: g_y = lrelu(x @ W_first + b)  (f32x2) ----------------
__global__ __launch_bounds__(128) void k_gemm1(const float* __restrict__ A,
                                               const float* __restrict__ W,
                                               const float* __restrict__ bias, int N) {
    __shared__ float As[128][33];
    __shared__ float Ws[32][48];
    int tid = threadIdx.x;
    int ty = tid >> 3, tx = tid & 7;          // 16 x 8
    int base = blockIdx.x * 128;
    unsigned long long acc[8][3];
#pragma unroll
    for (int r = 0; r < 8; ++r)
#pragma unroll
        for (int p = 0; p < 3; ++p) acc[r][p] = 0ull;

#pragma unroll 1
    for (int k0 = 0; k0 < FIN; k0 += 32) {
#pragma unroll
        for (int t = 0; t < 8; ++t) {
            int idx = tid + t * 128;          // 0..1023 float4
            int r = idx >> 3, q = idx & 7;
            float4 v = make_float4(0.f, 0.f, 0.f, 0.f);
            int gr = base + r;
            if (gr < N) v = *(const float4*)(A + (size_t)gr * FIN + k0 + q * 4);
            As[r][q * 4 + 0] = v.x; As[r][q * 4 + 1] = v.y;
            As[r][q * 4 + 2] = v.z; As[r][q * 4 + 3] = v.w;
        }
#pragma unroll
        for (int t = 0; t < 12; ++t) {
            int idx = tid + t * 128;          // 0..1535
            int k = idx / 48, j = idx % 48;
            Ws[k][j] = W[(k0 + k) * 48 + j];
        }
        __syncthreads();
#pragma unroll 8
        for (int kk = 0; kk < 32; ++kk) {
            unsigned long long a2[8], w2[3];
            const float2* wrow = (const float2*)&Ws[kk][tx * 6];
#pragma unroll
            for (int p = 0; p < 3; ++p) {
                float2 w = wrow[p];
                w2[p] = pack2(w.x, w.y);
            }
#pragma unroll
            for (int r = 0; r < 8; ++r) {
                float a = As[ty * 8 + r][kk];
                a2[r] = pack2(a, a);
            }
#pragma unroll
            for (int r = 0; r < 8; ++r)
#pragma unroll
                for (int p = 0; p < 3; ++p) acc[r][p] = fma2(a2[r], w2[p], acc[r][p]);
        }
        __syncthreads();
    }
#pragma unroll
    for (int r = 0; r < 8; ++r) {
        int gr = base + ty * 8 + r;
        if (gr >= N) continue;
#pragma unroll
        for (int p = 0; p < 3; ++p) {
            float lo, hi;
            unpack2(acc[r][p], lo, hi);
            int j = tx * 6 + p * 2;
            g_y[(size_t)gr * HID + j]     = lrelu(lo + bias[j]);
            g_y[(size_t)gr * HID + j + 1] = lrelu(hi + bias[j + 1]);
        }
    }
}

// ---------------- GEMM H: g_hw = y @ Wfold + bfold; g_cat <- a*y+c (f32x2) ----------------
__global__ __launch_bounds__(128) void k_gemm_h(int colOff, int N) {
    const float* __restrict__ Y = g_y;
    __shared__ float As[128][49];
    __shared__ float Ws[48][48];
    int tid = threadIdx.x;
    int ty = tid >> 3, tx = tid & 7;
    int base = blockIdx.x * 128;
    unsigned long long acc[8][3];
#pragma unroll
    for (int r = 0; r < 8; ++r)
#pragma unroll
        for (int p = 0; p < 3; ++p) acc[r][p] = 0ull;

#pragma unroll
    for (int t = 0; t < 12; ++t) {
        int idx = tid + t * 128;              // 0..1535 float4
        int r = idx / 12, q = idx % 12;
        float4 v = make_float4(0.f, 0.f, 0.f, 0.f);
        int gr = base + r;
        if (gr < N) v = *(const float4*)(Y + (size_t)gr * HID + q * 4);
        int j = q * 4;
        As[r][j + 0] = v.x; As[r][j + 1] = v.y; As[r][j + 2] = v.z; As[r][j + 3] = v.w;
        if (gr < N) {
            float* dst = g_cat + (size_t)gr * CAT + colOff + j;
            dst[0] = g_scale[j + 0] * v.x + g_shift[j + 0];
            dst[1] = g_scale[j + 1] * v.y + g_shift[j + 1];
            dst[2] = g_scale[j + 2] * v.z + g_shift[j + 2];
            dst[3] = g_scale[j + 3] * v.w + g_shift[j + 3];
        }
    }
#pragma unroll
    for (int t = 0; t < 18; ++t) {
        int idx = tid + t * 128;              // 0..2303
        Ws[idx / 48][idx % 48] = g_wfold[idx];
    }
    __syncthreads();
#pragma unroll 8
    for (int kk = 0; kk < 48; ++kk) {
        unsigned long long a2[8], w2[3];
        const float2* wrow = (const float2*)&Ws[kk][tx * 6];
#pragma unroll
        for (int p = 0; p < 3; ++p) {
            float2 w = wrow[p];
            w2[p] = pack2(w.x, w.y);
        }
#pragma unroll
        for (int r = 0; r < 8; ++r) {
            float a = As[ty * 8 + r][kk];
            a2[r] = pack2(a, a);
        }
#pragma unroll
        for (int r = 0; r < 8; ++r)
#pragma unroll
            for (int p = 0; p < 3; ++p) acc[r][p] = fma2(a2[r], w2[p], acc[r][p]);
    }
#pragma unroll
    for (int r = 0; r < 8; ++r) {
        int gr = base + ty * 8 + r;
        if (gr >= N) continue;
#pragma unroll
        for (int p = 0; p < 3; ++p) {
            float lo, hi;
            unpack2(acc[r][p], lo, hi);
            int j = tx * 6 + p * 2;
            g_hw[(size_t)gr * HID + j]     = lo + g_bfold[j];
            g_hw[(size_t)gr * HID + j + 1] = hi + g_bfold[j + 1];
        }
    }
}

// ---------------- stats (deterministic 2-level column mean/var) ----------------
__global__ void k_stats1(int sel, int N) {
    const float* __restrict__ Y = (sel == 0) ? g_y : (g_cat + 96);
    int ld = (sel == 0) ? HID : CAT;
    int col = threadIdx.x % 48, rs = threadIdx.x / 48;    // blockDim 384
    float s = 0.f, q = 0.f;
    for (int r = blockIdx.x * 8 + rs; r < N; r += 128 * 8) {
        float v = Y[(size_t)r * ld + col];
        s += v; q += v * v;
    }
    __shared__ float sh[384], shq[384];
    sh[threadIdx.x] = s; shq[threadIdx.x] = q;
    __syncthreads();
    if (threadIdx.x < 48) {
#pragma unroll
        for (int i = 1; i < 8; ++i) { s += sh[i * 48 + col]; q += shq[i * 48 + col]; }
        g_part[blockIdx.x * 96 + col] = s;
        g_part[blockIdx.x * 96 + 48 + col] = q;
    }
}

// fused: BN affine (scale/shift) + fold into next-layer weight
__global__ void k_bnfold(const float* __restrict__ g, const float* __restrict__ b,
                         const float* __restrict__ Wc, float invN) {
    int j = threadIdx.x;
    if (j < 48) {
        float s = 0.f, q = 0.f;
        for (int blk = 0; blk < 128; ++blk) { s += g_part[blk * 96 + j]; q += g_part[blk * 96 + 48 + j]; }
        float mean = s * invN;
        float var = q * invN - mean * mean;
        float a = g[j] * rsqrtf(var + EPSB);
        g_scale[j] = a;
        g_shift[j] = b[j] - mean * a;
    }
    __syncthreads();
    for (int idx = threadIdx.x; idx < HID * HID; idx += blockDim.x)
        g_wfold[idx] = g_scale[idx / HID] * Wc[idx];
    if (threadIdx.x < HID) {
        float s = 0.f;
        for (int k = 0; k < HID; ++k) s += g_shift[k] * Wc[k * HID + threadIdx.x];
        g_bfold[threadIdx.x] = s;
    }
}

__global__ void k_bnfold_out(const float* __restrict__ g, const float* __restrict__ b,
                             const float* __restrict__ Wout, const float* __restrict__ bout,
                             float invN) {
    int j = threadIdx.x;
    if (j < 48) {
        float s = 0.f, q = 0.f;
        for (int blk = 0; blk < 128; ++blk) { s += g_part[blk * 96 + j]; q += g_part[blk * 96 + 48 + j]; }
        float mean = s * invN;
        float var = q * invN - mean * mean;
        float a = g[j] * rsqrtf(var + EPSB);
        g_scale[j] = a;
        g_shift[j] = b[j] - mean * a;
    }
    __syncthreads();
    for (int idx = threadIdx.x; idx < CAT * NC; idx += blockDim.x) {
        int k = idx / NC;
        g_wout[idx] = (k < 96) ? Wout[idx] : g_scale[k - 96] * Wout[idx];
    }
    if (threadIdx.x < NC) {
        float s = bout[threadIdx.x];
        for (int k = 0; k < HID; ++k) s += g_shift[k] * Wout[(96 + k) * NC + threadIdx.x];
        g_bout[threadIdx.x] = s;
    }
}

// ---------------- sparse conv (gather, CSR by dst) ----------------
__global__ void k_conv(const float* __restrict__ bias, int outSel, int N) {
    float* __restrict__ out = (outSel == 0) ? g_y : (g_cat + 96);
    int ld = (outSel == 0) ? HID : CAT;
    int g = blockIdx.x * blockDim.x + threadIdx.x;
    int node = g >> 2;
    if (node >= N) return;
    int sub = g & 3;                          // 12 floats each
    float di = g_dinv[node];
    float s = di * di;                        // self-loop norm
    const float4* hs = (const float4*)(g_hw + (size_t)node * HID + sub * 12);
    float4 a0 = hs[0], a1 = hs[1], a2 = hs[2];
    float4 c0 = make_float4(s * a0.x, s * a0.y, s * a0.z, s * a0.w);
    float4 c1 = make_float4(s * a1.x, s * a1.y, s * a1.z, s * a1.w);
    float4 c2 = make_float4(s * a2.x, s * a2.y, s * a2.z, s * a2.w);
    int beg = g_rowptr[node], end = g_rowptr[node + 1];
#pragma unroll 2
    for (int j = beg; j < end; ++j) {
        float2 e = g_ec[j];
        int src = __float_as_int(e.y);
        float cf = e.x;
        const float4* p = (const float4*)(g_hw + (size_t)src * HID + sub * 12);
        float4 v0 = p[0], v1 = p[1], v2 = p[2];
        c0.x += cf * v0.x; c0.y += cf * v0.y; c0.z += cf * v0.z; c0.w += cf * v0.w;
        c1.x += cf * v1.x; c1.y += cf * v1.y; c1.z += cf * v1.z; c1.w += cf * v1.w;
        c2.x += cf * v2.x; c2.y += cf * v2.y; c2.z += cf * v2.z; c2.w += cf * v2.w;
    }
    int cb = sub * 12;
    const float4* bp = (const float4*)(bias + cb);
    float4 b0 = bp[0], b1 = bp[1], b2 = bp[2];
    float4 o0 = make_float4(lrelu(c0.x + b0.x), lrelu(c0.y + b0.y), lrelu(c0.z + b0.z), lrelu(c0.w + b0.w));
    float4 o1 = make_float4(lrelu(c1.x + b1.x), lrelu(c1.y + b1.y), lrelu(c1.z + b1.z), lrelu(c1.w + b1.w));
    float4 o2 = make_float4(lrelu(c2.x + b2.x), lrelu(c2.y + b2.y), lrelu(c2.z + b2.z), lrelu(c2.w + b2.w));
    float4* op = (float4*)(out + (size_t)node * ld + cb);
    op[0] = o0; op[1] = o1; op[2] = o2;
}

// ---------------- head GEMM + log_softmax ----------------
__global__ __launch_bounds__(128) void k_gemm_out(float* __restrict__ out, int N) {
    __shared__ float As[128][49];
    __shared__ float Ws[48][40];
    int tid = threadIdx.x;
    int ty = tid >> 3, tx = tid & 7;          // 16 x 8; 8 rows x 5 cols per thread
    int base = blockIdx.x * 128;
    float acc[8][5];
#pragma unroll
    for (int r = 0; r < 8; ++r)
#pragma unroll
        for (int c = 0; c < 5; ++c) acc[r][c] = 0.f;

#pragma unroll 1
    for (int k0 = 0; k0 < CAT; k0 += 48) {
#pragma unroll
        for (int t = 0; t < 12; ++t) {
            int idx = tid + t * 128;          // float4
            int r = idx / 12, q = idx % 12;
            float4 v = make_float4(0.f, 0.f, 0.f, 0.f);
            int gr = base + r;
            if (gr < N) v = *(const float4*)(g_cat + (size_t)gr * CAT + k0 + q * 4);
            int j = q * 4;
            As[r][j + 0] = v.x; As[r][j + 1] = v.y; As[r][j + 2] = v.z; As[r][j + 3] = v.w;
        }
#pragma unroll
        for (int t = 0; t < 15; ++t) {
            int idx = tid + t * 128;          // 0..1919
            Ws[idx / 40][idx % 40] = g_wout[k0 * 40 + idx];
        }
        __syncthreads();
#pragma unroll 8
        for (int kk = 0; kk < 48; ++kk) {
            float a[8], w[5];
#pragma unroll
            for (int r = 0; r < 8; ++r) a[r] = As[ty * 8 + r][kk];
#pragma unroll
            for (int c = 0; c < 5; ++c) w[c] = Ws[kk][tx * 5 + c];
#pragma unroll
            for (int r = 0; r < 8; ++r)
#pragma unroll
                for (int c = 0; c < 5; ++c) acc[r][c] += a[r] * w[c];
        }
        __syncthreads();
    }
    // log_softmax over 40 cols: 8-lane groups (tx 0..7) hold one row
#pragma unroll
    for (int r = 0; r < 8; ++r) {
        int gr = base + ty * 8 + r;
        float v[5];
        float m = -1e30f;
#pragma unroll
        for (int c = 0; c < 5; ++c) { v[c] = acc[r][c] + g_bout[tx * 5 + c]; m = fmaxf(m, v[c]); }
#pragma unroll
        for (int off = 1; off < 8; off <<= 1) m = fmaxf(m, __shfl_xor_sync(0xffffffffu, m, off));
        float se = 0.f;
#pragma unroll
        for (int c = 0; c < 5; ++c) se += __expf(v[c] - m);
#pragma unroll
        for (int off = 1; off < 8; off <<= 1) se += __shfl_xor_sync(0xffffffffu, se, off);
        float ls = __logf(se);
        if (gr < N) {
#pragma unroll
            for (int c = 0; c < 5; ++c) out[(size_t)gr * NC + tx * 5 + c] = v[c] - m - ls;
        }
    }
}

// ---------------- launch ----------------
extern "C" void kernel_launch(void* const* d_in, const int* in_sizes, int n_in,
                              void* d_out, int out_size) {
    const float* x    = (const float*)d_in[0];
    const int*   ei   = (const int*)d_in[1];     // int32 (JAX demotes int64 without x64)
    const float* ew   = (const float*)d_in[2];
    const float* Wf   = (const float*)d_in[3];
    const float* bf   = (const float*)d_in[4];
    const float* bn1g = (const float*)d_in[5];
    const float* bn1b = (const float*)d_in[6];
    const float* Wc1  = (const float*)d_in[7];
    const float* bc1  = (const float*)d_in[8];
    const float* bn2g = (const float*)d_in[9];
    const float* bn2b = (const float*)d_in[10];
    const float* Wc2  = (const float*)d_in[11];
    const float* bc2  = (const float*)d_in[12];
    const float* bn3g = (const float*)d_in[13];
    const float* bn3b = (const float*)d_in[14];
    const float* Wout = (const float*)d_in[15];
    const float* bout = (const float*)d_in[16];
    float* out = (float*)d_out;

    int N = in_sizes[0] / FIN;
    int E = in_sizes[2];
    float invN = 1.0f / (float)N;
    int SB = (N + 1023) / 1024;
    int gN = (N + 255) / 256;
    int gE = (E + 255) / 256;
    int gT = (N + 127) / 128;       // gemm row blocks
    int gC = (4 * N + 255) / 256;   // conv

    // graph structure (gemm1 placed at launch index 5 so ncu -s 5 profiles it)
    k_zero<<<gN, 256>>>(N);                      // 0
    k_degcnt<<<gE, 256>>>(ei, ew, E);            // 1
    k_scanA<<<SB, 1024>>>(N);                    // 2 (includes dinv)
    k_scanB<<<1, 1>>>(SB, N);                    // 3
    k_scanC<<<gN, 256>>>(N);                     // 4
    k_gemm1<<<gT, 128>>>(x, Wf, bf, N);          // 5  <-- profiled
    k_fill<<<gE, 256>>>(ei, ew, E);              // 6

    // layer 1
    k_stats1<<<128, 384>>>(0, N);
    k_bnfold<<<1, 256>>>(bn1g, bn1b, Wc1, invN);
    k_gemm_h<<<gT, 128>>>(0, N);
    k_conv<<<gC, 256>>>(bc1, 0, N);

    // layer 2
    k_stats1<<<128, 384>>>(0, N);
    k_bnfold<<<1, 256>>>(bn2g, bn2b, Wc2, invN);
    k_gemm_h<<<gT, 128>>>(HID, N);
    k_conv<<<gC, 256>>>(bc2, 1, N);

    // layer 3 stats folded into output weights
    k_stats1<<<128, 384>>>(1, N);
    k_bnfold_out<<<1, 256>>>(bn3g, bn3b, Wout, bout, invN);

    k_gemm_out<<<gT, 128>>>(out, N);
}

// round 5
// speedup vs baseline: 1.1505x; 1.0970x over previous
#include <cuda_runtime.h>

#define NMAX 100000
#define EMAX 1600000
#define FIN  128
#define HID  48
#define NC   40
#define CAT  144
#define EPSB 1e-5f
#define SLOPE 0.01f

// ---------------- device scratch (static, allocation-free) ----------------
__device__ __align__(16) float  g_y[NMAX * HID];      // y (pre-BN, post-lrelu) per layer
__device__ __align__(16) float  g_hw[NMAX * HID];     // h @ Wc (BN-folded)
__device__ __align__(16) float  g_cat[NMAX * CAT];    // [h1 | h2 | y3(raw)]
__device__ float  g_deg[NMAX];
__device__ float  g_dinv[NMAX];
__device__ int    g_cnt[NMAX];
__device__ int    g_rowptr[NMAX + 1];
__device__ int    g_wp[NMAX];
__device__ int    g_bsum[256];
__device__ __align__(16) float2 g_ec[EMAX];           // {coef, src-as-float-bits}
__device__ float  g_part[128 * 2 * HID];              // stats partials
__device__ float  g_scale[HID], g_shift[HID];         // BN affine a, c
__device__ float  g_wfold[HID * HID], g_bfold[HID];
__device__ float  g_wout[CAT * NC], g_bout[NC];

__device__ __forceinline__ float lrelu(float v) { return v >= 0.f ? v : SLOPE * v; }

// ---- packed f32x2 helpers (FFMA2 only reachable via PTX) ----
__device__ __forceinline__ unsigned long long fma2(unsigned long long a,
                                                   unsigned long long b,
                                                   unsigned long long c) {
    unsigned long long d;
    asm("fma.rn.f32x2 %0, %1, %2, %3;" : "=l"(d) : "l"(a), "l"(b), "l"(c));
    return d;
}
__device__ __forceinline__ unsigned long long pack2(float lo, float hi) {
    unsigned long long r;
    asm("mov.b64 %0, {%1, %2};" : "=l"(r) : "f"(lo), "f"(hi));
    return r;
}
__device__ __forceinline__ void unpack2(unsigned long long v, float& lo, float& hi) {
    asm("mov.b64 {%0, %1}, %2;" : "=f"(lo), "=f"(hi) : "l"(v));
}

// ---------------- graph-structure kernels ----------------
__global__ void k_degcnt(const int* __restrict__ ei, const float* __restrict__ ew, int E) {
    int e = blockIdx.x * blockDim.x + threadIdx.x;
    if (e >= E) return;
    int dst = ei[E + e];
    atomicAdd(&g_deg[dst], ew[e]);
    atomicAdd(&g_cnt[dst], 1);
}

// block scan over counts (+ fused dinv)
__global__ void k_scanA(int N) {
    __shared__ int s[1024];
    int tid = threadIdx.x;
    int i = blockIdx.x * 1024 + tid;
    int v = (i < N) ? g_cnt[i] : 0;
    if (i < N) g_dinv[i] = rsqrtf(g_deg[i] + 1.0f);   // +1 = self-loop weight
    s[tid] = v;
    __syncthreads();
    for (int off = 1; off < 1024; off <<= 1) {
        int t = (tid >= off) ? s[tid - off] : 0;
        __syncthreads();
        s[tid] += t;
        __syncthreads();
    }
    if (i < N) g_rowptr[i] = s[tid] - v;       // exclusive within block
    if (tid == 1023) g_bsum[blockIdx.x] = s[1023];
}

// add cross-block offsets (computes its own prefix of g_bsum; no serial kernel)
__global__ void k_scanC(int SB, int N) {
    __shared__ int sb[128];
    __shared__ int tmp[128];
    int tid = threadIdx.x;
    if (tid < 128) sb[tid] = (tid < SB) ? g_bsum[tid] : 0;
    __syncthreads();
    // exclusive prefix for this block
    if (tid < 128) tmp[tid] = (tid < blockIdx.x) ? sb[tid] : 0;
    __syncthreads();
    for (int s = 64; s > 0; s >>= 1) {
        if (tid < s) tmp[tid] += tmp[tid + s];
        __syncthreads();
    }
    int off = tmp[0];
    __syncthreads();
    // grand total (for rowptr[N])
    if (tid < 128) tmp[tid] = sb[tid];
    __syncthreads();
    for (int s = 64; s > 0; s >>= 1) {
        if (tid < s) tmp[tid] += tmp[tid + s];
        __syncthreads();
    }
    int total = tmp[0];

    int i = blockIdx.x * 1024 + tid;
    if (i < N) {
        int v = g_rowptr[i] + off;
        g_rowptr[i] = v;
        g_wp[i] = v;
    }
    if (blockIdx.x == 0 && tid == 0) g_rowptr[N] = total;
}

__global__ void k_fill(const int* __restrict__ ei, const float* __restrict__ ew, int E) {
    int e = blockIdx.x * blockDim.x + threadIdx.x;
    if (e >= E) return;
    int src = ei[e];
    int dst = ei[E + e];
    int pos = atomicAdd(&g_wp[dst], 1);
    float coef = g_dinv[src] * ew[e] * g_dinv[dst];
    g_ec[pos] = make_float2(coef, __int_as_float(src));
}

// ---------------- GEMM 1: g_y = lrelu(x @ W_first + b)  (f32x2) ----------------
__global__ __launch_bounds__(128) void k_gemm1(const float* __restrict__ A,
                                               const float* __restrict__ W,
                                               const float* __restrict__ bias, int N) {
    __shared__ float As[128][33];
    __shared__ float Ws[32][48];
    int tid = threadIdx.x;
    int ty = tid >> 3, tx = tid & 7;          // 16 x 8
    int base = blockIdx.x * 128;
    unsigned long long acc[8][3];
#pragma unroll
    for (int r = 0; r < 8; ++r)
#pragma unroll
        for (int p = 0; p < 3; ++p) acc[r][p] = 0ull;

#pragma unroll 1
    for (int k0 = 0; k0 < FIN; k0 += 32) {
#pragma unroll
        for (int t = 0; t < 8; ++t) {
            int idx = tid + t * 128;          // 0..1023 float4
            int r = idx >> 3, q = idx & 7;
            float4 v = make_float4(0.f, 0.f, 0.f, 0.f);
            int gr = base + r;
            if (gr < N) v = *(const float4*)(A + (size_t)gr * FIN + k0 + q * 4);
            As[r][q * 4 + 0] = v.x; As[r][q * 4 + 1] = v.y;
            As[r][q * 4 + 2] = v.z; As[r][q * 4 + 3] = v.w;
        }
#pragma unroll
        for (int t = 0; t < 12; ++t) {
            int idx = tid + t * 128;          // 0..1535
            int k = idx / 48, j = idx % 48;
            Ws[k][j] = W[(k0 + k) * 48 + j];
        }
        __syncthreads();
#pragma unroll 8
        for (int kk = 0; kk < 32; ++kk) {
            unsigned long long a2[8], w2[3];
            const float2* wrow = (const float2*)&Ws[kk][tx * 6];
#pragma unroll
            for (int p = 0; p < 3; ++p) {
                float2 w = wrow[p];
                w2[p] = pack2(w.x, w.y);
            }
#pragma unroll
            for (int r = 0; r < 8; ++r) {
                float a = As[ty * 8 + r][kk];
                a2[r] = pack2(a, a);
            }
#pragma unroll
            for (int r = 0; r < 8; ++r)
#pragma unroll
                for (int p = 0; p < 3; ++p) acc[r][p] = fma2(a2[r], w2[p], acc[r][p]);
        }
        __syncthreads();
    }
#pragma unroll
    for (int r = 0; r < 8; ++r) {
        int gr = base + ty * 8 + r;
        if (gr >= N) continue;
#pragma unroll
        for (int p = 0; p < 3; ++p) {
            float lo, hi;
            unpack2(acc[r][p], lo, hi);
            int j = tx * 6 + p * 2;
            g_y[(size_t)gr * HID + j]     = lrelu(lo + bias[j]);
            g_y[(size_t)gr * HID + j + 1] = lrelu(hi + bias[j + 1]);
        }
    }
}

// ---------------- GEMM H: g_hw = y @ Wfold + bfold; g_cat <- a*y+c (f32x2) ----------------
__global__ __launch_bounds__(128) void k_gemm_h(int colOff, int N) {
    const float* __restrict__ Y = g_y;
    __shared__ float As[128][49];
    __shared__ float Ws[48][48];
    int tid = threadIdx.x;
    int ty = tid >> 3, tx = tid & 7;
    int base = blockIdx.x * 128;
    unsigned long long acc[8][3];
#pragma unroll
    for (int r = 0; r < 8; ++r)
#pragma unroll
        for (int p = 0; p < 3; ++p) acc[r][p] = 0ull;

#pragma unroll
    for (int t = 0; t < 12; ++t) {
        int idx = tid + t * 128;              // 0..1535 float4
        int r = idx / 12, q = idx % 12;
        float4 v = make_float4(0.f, 0.f, 0.f, 0.f);
        int gr = base + r;
        if (gr < N) v = *(const float4*)(Y + (size_t)gr * HID + q * 4);
        int j = q * 4;
        As[r][j + 0] = v.x; As[r][j + 1] = v.y; As[r][j + 2] = v.z; As[r][j + 3] = v.w;
        if (gr < N) {
            float* dst = g_cat + (size_t)gr * CAT + colOff + j;
            dst[0] = g_scale[j + 0] * v.x + g_shift[j + 0];
            dst[1] = g_scale[j + 1] * v.y + g_shift[j + 1];
            dst[2] = g_scale[j + 2] * v.z + g_shift[j + 2];
            dst[3] = g_scale[j + 3] * v.w + g_shift[j + 3];
        }
    }
#pragma unroll
    for (int t = 0; t < 18; ++t) {
        int idx = tid + t * 128;              // 0..2303
        Ws[idx / 48][idx % 48] = g_wfold[idx];
    }
    __syncthreads();
#pragma unroll 8
    for (int kk = 0; kk < 48; ++kk) {
        unsigned long long a2[8], w2[3];
        const float2* wrow = (const float2*)&Ws[kk][tx * 6];
#pragma unroll
        for (int p = 0; p < 3; ++p) {
            float2 w = wrow[p];
            w2[p] = pack2(w.x, w.y);
        }
#pragma unroll
        for (int r = 0; r < 8; ++r) {
            float a = As[ty * 8 + r][kk];
            a2[r] = pack2(a, a);
        }
#pragma unroll
        for (int r = 0; r < 8; ++r)
#pragma unroll
            for (int p = 0; p < 3; ++p) acc[r][p] = fma2(a2[r], w2[p], acc[r][p]);
    }
#pragma unroll
    for (int r = 0; r < 8; ++r) {
        int gr = base + ty * 8 + r;
        if (gr >= N) continue;
#pragma unroll
        for (int p = 0; p < 3; ++p) {
            float lo, hi;
            unpack2(acc[r][p], lo, hi);
            int j = tx * 6 + p * 2;
            g_hw[(size_t)gr * HID + j]     = lo + g_bfold[j];
            g_hw[(size_t)gr * HID + j + 1] = hi + g_bfold[j + 1];
        }
    }
}

// ---------------- stats (deterministic 2-level column mean/var) ----------------
__global__ void k_stats1(int sel, int N) {
    const float* __restrict__ Y = (sel == 0) ? g_y : (g_cat + 96);
    int ld = (sel == 0) ? HID : CAT;
    int col = threadIdx.x % 48, rs = threadIdx.x / 48;    // blockDim 384
    float s = 0.f, q = 0.f;
    for (int r = blockIdx.x * 8 + rs; r < N; r += 128 * 8) {
        float v = Y[(size_t)r * ld + col];
        s += v; q += v * v;
    }
    __shared__ float sh[384], shq[384];
    sh[threadIdx.x] = s; shq[threadIdx.x] = q;
    __syncthreads();
    if (threadIdx.x < 48) {
#pragma unroll
        for (int i = 1; i < 8; ++i) { s += sh[i * 48 + col]; q += shq[i * 48 + col]; }
        g_part[blockIdx.x * 96 + col] = s;
        g_part[blockIdx.x * 96 + 48 + col] = q;
    }
}

// fused: BN affine (scale/shift) + fold into next-layer weight
__global__ void k_bnfold(const float* __restrict__ g, const float* __restrict__ b,
                         const float* __restrict__ Wc, float invN) {
    int j = threadIdx.x;
    if (j < 48) {
        float s = 0.f, q = 0.f;
        for (int blk = 0; blk < 128; ++blk) { s += g_part[blk * 96 + j]; q += g_part[blk * 96 + 48 + j]; }
        float mean = s * invN;
        float var = q * invN - mean * mean;
        float a = g[j] * rsqrtf(var + EPSB);
        g_scale[j] = a;
        g_shift[j] = b[j] - mean * a;
    }
    __syncthreads();
    for (int idx = threadIdx.x; idx < HID * HID; idx += blockDim.x)
        g_wfold[idx] = g_scale[idx / HID] * Wc[idx];
    if (threadIdx.x < HID) {
        float s = 0.f;
        for (int k = 0; k < HID; ++k) s += g_shift[k] * Wc[k * HID + threadIdx.x];
        g_bfold[threadIdx.x] = s;
    }
}

__global__ void k_bnfold_out(const float* __restrict__ g, const float* __restrict__ b,
                             const float* __restrict__ Wout, const float* __restrict__ bout,
                             float invN) {
    int j = threadIdx.x;
    if (j < 48) {
        float s = 0.f, q = 0.f;
        for (int blk = 0; blk < 128; ++blk) { s += g_part[blk * 96 + j]; q += g_part[blk * 96 + 48 + j]; }
        float mean = s * invN;
        float var = q * invN - mean * mean;
        float a = g[j] * rsqrtf(var + EPSB);
        g_scale[j] = a;
        g_shift[j] = b[j] - mean * a;
    }
    __syncthreads();
    for (int idx = threadIdx.x; idx < CAT * NC; idx += blockDim.x) {
        int k = idx / NC;
        g_wout[idx] = (k < 96) ? Wout[idx] : g_scale[k - 96] * Wout[idx];
    }
    if (threadIdx.x < NC) {
        float s = bout[threadIdx.x];
        for (int k = 0; k < HID; ++k) s += g_shift[k] * Wout[(96 + k) * NC + threadIdx.x];
        g_bout[threadIdx.x] = s;
    }
}

// ---------------- sparse conv (gather, CSR by dst) ----------------
__global__ void k_conv(const float* __restrict__ bias, int outSel, int N) {
    float* __restrict__ out = (outSel == 0) ? g_y : (g_cat + 96);
    int ld = (outSel == 0) ? HID : CAT;
    int g = blockIdx.x * blockDim.x + threadIdx.x;
    int node = g >> 2;
    if (node >= N) return;
    int sub = g & 3;                          // 12 floats each
    float di = g_dinv[node];
    float s = di * di;                        // self-loop norm
    const float4* hs = (const float4*)(g_hw + (size_t)node * HID + sub * 12);
    float4 a0 = hs[0], a1 = hs[1], a2 = hs[2];
    float4 c0 = make_float4(s * a0.x, s * a0.y, s * a0.z, s * a0.w);
    float4 c1 = make_float4(s * a1.x, s * a1.y, s * a1.z, s * a1.w);
    float4 c2 = make_float4(s * a2.x, s * a2.y, s * a2.z, s * a2.w);
    int beg = g_rowptr[node], end = g_rowptr[node + 1];
#pragma unroll 2
    for (int j = beg; j < end; ++j) {
        float2 e = g_ec[j];
        int src = __float_as_int(e.y);
        float cf = e.x;
        const float4* p = (const float4*)(g_hw + (size_t)src * HID + sub * 12);
        float4 v0 = p[0], v1 = p[1], v2 = p[2];
        c0.x += cf * v0.x; c0.y += cf * v0.y; c0.z += cf * v0.z; c0.w += cf * v0.w;
        c1.x += cf * v1.x; c1.y += cf * v1.y; c1.z += cf * v1.z; c1.w += cf * v1.w;
        c2.x += cf * v2.x; c2.y += cf * v2.y; c2.z += cf * v2.z; c2.w += cf * v2.w;
    }
    int cb = sub * 12;
    const float4* bp = (const float4*)(bias + cb);
    float4 b0 = bp[0], b1 = bp[1], b2 = bp[2];
    float4 o0 = make_float4(lrelu(c0.x + b0.x), lrelu(c0.y + b0.y), lrelu(c0.z + b0.z), lrelu(c0.w + b0.w));
    float4 o1 = make_float4(lrelu(c1.x + b1.x), lrelu(c1.y + b1.y), lrelu(c1.z + b1.z), lrelu(c1.w + b1.w));
    float4 o2 = make_float4(lrelu(c2.x + b2.x), lrelu(c2.y + b2.y), lrelu(c2.z + b2.z), lrelu(c2.w + b2.w));
    float4* op = (float4*)(out + (size_t)node * ld + cb);
    op[0] = o0; op[1] = o1; op[2] = o2;
}

// ---------------- head GEMM + log_softmax (f32x2) ----------------
__global__ __launch_bounds__(128) void k_gemm_out(float* __restrict__ out, int N) {
    __shared__ float As[128][49];
    __shared__ float Ws[48][40];
    int tid = threadIdx.x;
    int ty = tid >> 3, tx = tid & 7;          // 16 x 8; 8 rows x 5 cols per thread
    int base = blockIdx.x * 128;
    unsigned long long acc2[8][2];
    float acc1[8];
#pragma unroll
    for (int r = 0; r < 8; ++r) { acc2[r][0] = 0ull; acc2[r][1] = 0ull; acc1[r] = 0.f; }

#pragma unroll 1
    for (int k0 = 0; k0 < CAT; k0 += 48) {
#pragma unroll
        for (int t = 0; t < 12; ++t) {
            int idx = tid + t * 128;          // float4
            int r = idx / 12, q = idx % 12;
            float4 v = make_float4(0.f, 0.f, 0.f, 0.f);
            int gr = base + r;
            if (gr < N) v = *(const float4*)(g_cat + (size_t)gr * CAT + k0 + q * 4);
            int j = q * 4;
            As[r][j + 0] = v.x; As[r][j + 1] = v.y; As[r][j + 2] = v.z; As[r][j + 3] = v.w;
        }
#pragma unroll
        for (int t = 0; t < 15; ++t) {
            int idx = tid + t * 128;          // 0..1919
            Ws[idx / 40][idx % 40] = g_wout[k0 * 40 + idx];
        }
        __syncthreads();
#pragma unroll 8
        for (int kk = 0; kk < 48; ++kk) {
            float w0 = Ws[kk][tx * 5 + 0], w1 = Ws[kk][tx * 5 + 1];
            float w2 = Ws[kk][tx * 5 + 2], w3 = Ws[kk][tx * 5 + 3];
            float w4 = Ws[kk][tx * 5 + 4];
            unsigned long long wp0 = pack2(w0, w1), wp1 = pack2(w2, w3);
#pragma unroll
            for (int r = 0; r < 8; ++r) {
                float a = As[ty * 8 + r][kk];
                unsigned long long a2 = pack2(a, a);
                acc2[r][0] = fma2(a2, wp0, acc2[r][0]);
                acc2[r][1] = fma2(a2, wp1, acc2[r][1]);
                acc1[r] = fmaf(a, w4, acc1[r]);
            }
        }
        __syncthreads();
    }
    // log_softmax over 40 cols: 8-lane groups (tx 0..7) hold one row
#pragma unroll
    for (int r = 0; r < 8; ++r) {
        int gr = base + ty * 8 + r;
        float v[5];
        unpack2(acc2[r][0], v[0], v[1]);
        unpack2(acc2[r][1], v[2], v[3]);
        v[4] = acc1[r];
        float m = -1e30f;
#pragma unroll
        for (int c = 0; c < 5; ++c) { v[c] += g_bout[tx * 5 + c]; m = fmaxf(m, v[c]); }
#pragma unroll
        for (int off = 1; off < 8; off <<= 1) m = fmaxf(m, __shfl_xor_sync(0xffffffffu, m, off));
        float se = 0.f;
#pragma unroll
        for (int c = 0; c < 5; ++c) se += __expf(v[c] - m);
#pragma unroll
        for (int off = 1; off < 8; off <<= 1) se += __shfl_xor_sync(0xffffffffu, se, off);
        float ls = __logf(se);
        if (gr < N) {
#pragma unroll
            for (int c = 0; c < 5; ++c) out[(size_t)gr * NC + tx * 5 + c] = v[c] - m - ls;
        }
    }
}

// ---------------- launch ----------------
extern "C" void kernel_launch(void* const* d_in, const int* in_sizes, int n_in,
                              void* d_out, int out_size) {
    const float* x    = (const float*)d_in[0];
    const int*   ei   = (const int*)d_in[1];     // int32 (JAX demotes int64 without x64)
    const float* ew   = (const float*)d_in[2];
    const float* Wf   = (const float*)d_in[3];
    const float* bf   = (const float*)d_in[4];
    const float* bn1g = (const float*)d_in[5];
    const float* bn1b = (const float*)d_in[6];
    const float* Wc1  = (const float*)d_in[7];
    const float* bc1  = (const float*)d_in[8];
    const float* bn2g = (const float*)d_in[9];
    const float* bn2b = (const float*)d_in[10];
    const float* Wc2  = (const float*)d_in[11];
    const float* bc2  = (const float*)d_in[12];
    const float* bn3g = (const float*)d_in[13];
    const float* bn3b = (const float*)d_in[14];
    const float* Wout = (const float*)d_in[15];
    const float* bout = (const float*)d_in[16];
    float* out = (float*)d_out;

    int N = in_sizes[0] / FIN;
    int E = in_sizes[2];
    float invN = 1.0f / (float)N;
    int SB = (N + 1023) / 1024;
    int gE = (E + 255) / 256;
    int gT = (N + 127) / 128;       // gemm row blocks
    int gC = (4 * N + 255) / 256;   // conv

    // One-time host resources (streams/events/symbol addrs); identical work each call.
    static cudaStream_t s2 = nullptr;
    static cudaEvent_t evFork = nullptr, evJoin = nullptr;
    static void* degPtr = nullptr;
    static void* cntPtr = nullptr;
    if (s2 == nullptr) {
        cudaStreamCreateWithFlags(&s2, cudaStreamNonBlocking);
        cudaEventCreateWithFlags(&evFork, cudaEventDisableTiming);
        cudaEventCreateWithFlags(&evJoin, cudaEventDisableTiming);
        cudaGetSymbolAddress(&degPtr, g_deg);
        cudaGetSymbolAddress(&cntPtr, g_cnt);
    }

    // ---- fork: edge pipeline on s2, node pipeline on default stream ----
    cudaEventRecord(evFork, 0);
    cudaStreamWaitEvent(s2, evFork, 0);

    cudaMemsetAsync(degPtr, 0, (size_t)N * sizeof(float), s2);
    cudaMemsetAsync(cntPtr, 0, (size_t)N * sizeof(int), s2);
    k_degcnt<<<gE, 256, 0, s2>>>(ei, ew, E);
    k_scanA<<<SB, 1024, 0, s2>>>(N);
    k_scanC<<<SB, 1024, 0, s2>>>(SB, N);
    k_fill<<<gE, 256, 0, s2>>>(ei, ew, E);
    cudaEventRecord(evJoin, s2);

    // node pipeline (independent until conv1)
    k_gemm1<<<gT, 128>>>(x, Wf, bf, N);
    k_stats1<<<128, 384>>>(0, N);
    k_bnfold<<<1, 256>>>(bn1g, bn1b, Wc1, invN);
    k_gemm_h<<<gT, 128>>>(0, N);

    // ---- join, then serial layer chain ----
    cudaStreamWaitEvent(0, evJoin, 0);
    k_conv<<<gC, 256>>>(bc1, 0, N);

    k_stats1<<<128, 384>>>(0, N);
    k_bnfold<<<1, 256>>>(bn2g, bn2b, Wc2, invN);
    k_gemm_h<<<gT, 128>>>(HID, N);
    k_conv<<<gC, 256>>>(bc2, 1, N);

    k_stats1<<<128, 384>>>(1, N);
    k_bnfold_out<<<1, 256>>>(bn3g, bn3b, Wout, bout, invN);

    k_gemm_out<<<gT, 128>>>(out, N);
}

// round 6
// speedup vs baseline: 1.2311x; 1.0701x over previous
#include <cuda_runtime.h>
#include <cuda_fp16.h>

#define NMAX 100000
#define EMAX 1600000
#define FIN  128
#define HID  48
#define NC   40
#define CAT  144
#define EPSB 1e-5f
#define SLOPE 0.01f

// ---------------- device scratch (static, allocation-free) ----------------
__device__ __align__(16) float  g_y[NMAX * HID];      // y (pre-BN, post-lrelu) per layer
__device__ __align__(16) float  g_hw[NMAX * HID];     // h @ Wc (BN-folded), fp32
__device__ __align__(16) __half g_hwh[NMAX * HID];    // dinv-scaled hw, fp16 (conv gathers)
__device__ __align__(16) float  g_cat[NMAX * CAT];    // [h1 | h2 | y3(raw)]
__device__ float  g_deg[NMAX];
__device__ float  g_dinv[NMAX];
__device__ int    g_cnt[NMAX];
__device__ int    g_rowptr[NMAX + 1];
__device__ int    g_wp[NMAX];
__device__ int    g_bsum[256];
__device__ __align__(16) float2 g_ec[EMAX];           // {ew, src-as-float-bits}
__device__ float  g_part[128 * 2 * HID];              // stats partials
__device__ float  g_scale[HID], g_shift[HID];         // BN affine a, c
__device__ float  g_wfold[HID * HID], g_bfold[HID];
__device__ float  g_wout[CAT * NC], g_bout[NC];

__device__ __forceinline__ float lrelu(float v) { return v >= 0.f ? v : SLOPE * v; }

// ---- packed f32x2 helpers (FFMA2 only reachable via PTX) ----
__device__ __forceinline__ unsigned long long fma2(unsigned long long a,
                                                   unsigned long long b,
                                                   unsigned long long c) {
    unsigned long long d;
    asm("fma.rn.f32x2 %0, %1, %2, %3;" : "=l"(d) : "l"(a), "l"(b), "l"(c));
    return d;
}
__device__ __forceinline__ unsigned long long pack2(float lo, float hi) {
    unsigned long long r;
    asm("mov.b64 %0, {%1, %2};" : "=l"(r) : "f"(lo), "f"(hi));
    return r;
}
__device__ __forceinline__ void unpack2(unsigned long long v, float& lo, float& hi) {
    asm("mov.b64 {%0, %1}, %2;" : "=f"(lo), "=f"(hi) : "l"(v));
}
__device__ __forceinline__ float2 h2f(unsigned int u) {
    __half2 h = *reinterpret_cast<__half2*>(&u);
    return __half22float2(h);
}

// ---------------- graph-structure kernels ----------------
__global__ void k_degcnt(const int* __restrict__ ei, const float* __restrict__ ew, int E) {
    int e = blockIdx.x * blockDim.x + threadIdx.x;
    if (e >= E) return;
    int dst = ei[E + e];
    atomicAdd(&g_deg[dst], ew[e]);
    atomicAdd(&g_cnt[dst], 1);
}

// block scan over counts (+ fused dinv)
__global__ void k_scanA(int N) {
    __shared__ int s[1024];
    int tid = threadIdx.x;
    int i = blockIdx.x * 1024 + tid;
    int v = (i < N) ? g_cnt[i] : 0;
    if (i < N) g_dinv[i] = rsqrtf(g_deg[i] + 1.0f);   // +1 = self-loop weight
    s[tid] = v;
    __syncthreads();
    for (int off = 1; off < 1024; off <<= 1) {
        int t = (tid >= off) ? s[tid - off] : 0;
        __syncthreads();
        s[tid] += t;
        __syncthreads();
    }
    if (i < N) g_rowptr[i] = s[tid] - v;       // exclusive within block
    if (tid == 1023) g_bsum[blockIdx.x] = s[1023];
}

// add cross-block offsets (computes its own prefix of g_bsum; no serial kernel)
__global__ void k_scanC(int SB, int N) {
    __shared__ int sb[128];
    __shared__ int tmp[128];
    int tid = threadIdx.x;
    if (tid < 128) sb[tid] = (tid < SB) ? g_bsum[tid] : 0;
    __syncthreads();
    if (tid < 128) tmp[tid] = (tid < blockIdx.x) ? sb[tid] : 0;
    __syncthreads();
    for (int s = 64; s > 0; s >>= 1) {
        if (tid < s) tmp[tid] += tmp[tid + s];
        __syncthreads();
    }
    int off = tmp[0];
    __syncthreads();
    if (tid < 128) tmp[tid] = sb[tid];
    __syncthreads();
    for (int s = 64; s > 0; s >>= 1) {
        if (tid < s) tmp[tid] += tmp[tid + s];
        __syncthreads();
    }
    int total = tmp[0];

    int i = blockIdx.x * 1024 + tid;
    if (i < N) {
        int v = g_rowptr[i] + off;
        g_rowptr[i] = v;
        g_wp[i] = v;
    }
    if (blockIdx.x == 0 && tid == 0) g_rowptr[N] = total;
}

// build CSR records {ew, src} — no dinv gathers (dinv folded into hws)
__global__ void k_fill(const int* __restrict__ ei, const float* __restrict__ ew, int E) {
    int e = blockIdx.x * blockDim.x + threadIdx.x;
    if (e >= E) return;
    int src = ei[e];
    int dst = ei[E + e];
    int pos = atomicAdd(&g_wp[dst], 1);
    g_ec[pos] = make_float2(ew[e], __int_as_float(src));
}

// ---------------- GEMM 1: g_y = lrelu(x @ W_first + b)  (f32x2) ----------------
__global__ __launch_bounds__(128) void k_gemm1(const float* __restrict__ A,
                                               const float* __restrict__ W,
                                               const float* __restrict__ bias, int N) {
    __shared__ float As[128][33];
    __shared__ float Ws[32][48];
    int tid = threadIdx.x;
    int ty = tid >> 3, tx = tid & 7;          // 16 x 8
    int base = blockIdx.x * 128;
    unsigned long long acc[8][3];
#pragma unroll
    for (int r = 0; r < 8; ++r)
#pragma unroll
        for (int p = 0; p < 3; ++p) acc[r][p] = 0ull;

#pragma unroll 1
    for (int k0 = 0; k0 < FIN; k0 += 32) {
#pragma unroll
        for (int t = 0; t < 8; ++t) {
            int idx = tid + t * 128;          // 0..1023 float4
            int r = idx >> 3, q = idx & 7;
            float4 v = make_float4(0.f, 0.f, 0.f, 0.f);
            int gr = base + r;
            if (gr < N) v = *(const float4*)(A + (size_t)gr * FIN + k0 + q * 4);
            As[r][q * 4 + 0] = v.x; As[r][q * 4 + 1] = v.y;
            As[r][q * 4 + 2] = v.z; As[r][q * 4 + 3] = v.w;
        }
#pragma unroll
        for (int t = 0; t < 12; ++t) {
            int idx = tid + t * 128;          // 0..1535
            int k = idx / 48, j = idx % 48;
            Ws[k][j] = W[(k0 + k) * 48 + j];
        }
        __syncthreads();
#pragma unroll 8
        for (int kk = 0; kk < 32; ++kk) {
            unsigned long long a2[8], w2[3];
            const float2* wrow = (const float2*)&Ws[kk][tx * 6];
#pragma unroll
            for (int p = 0; p < 3; ++p) {
                float2 w = wrow[p];
                w2[p] = pack2(w.x, w.y);
            }
#pragma unroll
            for (int r = 0; r < 8; ++r) {
                float a = As[ty * 8 + r][kk];
                a2[r] = pack2(a, a);
            }
#pragma unroll
            for (int r = 0; r < 8; ++r)
#pragma unroll
                for (int p = 0; p < 3; ++p) acc[r][p] = fma2(a2[r], w2[p], acc[r][p]);
        }
        __syncthreads();
    }
#pragma unroll
    for (int r = 0; r < 8; ++r) {
        int gr = base + ty * 8 + r;
        if (gr >= N) continue;
#pragma unroll
        for (int p = 0; p < 3; ++p) {
            float lo, hi;
            unpack2(acc[r][p], lo, hi);
            int j = tx * 6 + p * 2;
            g_y[(size_t)gr * HID + j]     = lrelu(lo + bias[j]);
            g_y[(size_t)gr * HID + j + 1] = lrelu(hi + bias[j + 1]);
        }
    }
}

// ---- GEMM H: g_hw = y @ Wfold + bfold; g_hwh = dinv*g_hw (fp16); g_cat <- a*y+c ----
__global__ __launch_bounds__(128) void k_gemm_h(int colOff, int N) {
    const float* __restrict__ Y = g_y;
    __shared__ float As[128][49];
    __shared__ float Ws[48][48];
    int tid = threadIdx.x;
    int ty = tid >> 3, tx = tid & 7;
    int base = blockIdx.x * 128;
    unsigned long long acc[8][3];
#pragma unroll
    for (int r = 0; r < 8; ++r)
#pragma unroll
        for (int p = 0; p < 3; ++p) acc[r][p] = 0ull;

#pragma unroll
    for (int t = 0; t < 12; ++t) {
        int idx = tid + t * 128;              // 0..1535 float4
        int r = idx / 12, q = idx % 12;
        float4 v = make_float4(0.f, 0.f, 0.f, 0.f);
        int gr = base + r;
        if (gr < N) v = *(const float4*)(Y + (size_t)gr * HID + q * 4);
        int j = q * 4;
        As[r][j + 0] = v.x; As[r][j + 1] = v.y; As[r][j + 2] = v.z; As[r][j + 3] = v.w;
        if (gr < N) {
            float* dst = g_cat + (size_t)gr * CAT + colOff + j;
            dst[0] = g_scale[j + 0] * v.x + g_shift[j + 0];
            dst[1] = g_scale[j + 1] * v.y + g_shift[j + 1];
            dst[2] = g_scale[j + 2] * v.z + g_shift[j + 2];
            dst[3] = g_scale[j + 3] * v.w + g_shift[j + 3];
        }
    }
#pragma unroll
    for (int t = 0; t < 18; ++t) {
        int idx = tid + t * 128;              // 0..2303
        Ws[idx / 48][idx % 48] = g_wfold[idx];
    }
    __syncthreads();
#pragma unroll 8
    for (int kk = 0; kk < 48; ++kk) {
        unsigned long long a2[8], w2[3];
        const float2* wrow = (const float2*)&Ws[kk][tx * 6];
#pragma unroll
        for (int p = 0; p < 3; ++p) {
            float2 w = wrow[p];
            w2[p] = pack2(w.x, w.y);
        }
#pragma unroll
        for (int r = 0; r < 8; ++r) {
            float a = As[ty * 8 + r][kk];
            a2[r] = pack2(a, a);
        }
#pragma unroll
        for (int r = 0; r < 8; ++r)
#pragma unroll
            for (int p = 0; p < 3; ++p) acc[r][p] = fma2(a2[r], w2[p], acc[r][p]);
    }
#pragma unroll
    for (int r = 0; r < 8; ++r) {
        int gr = base + ty * 8 + r;
        if (gr >= N) continue;
        float dv = g_dinv[gr];
        __half2* hp = (__half2*)(g_hwh + (size_t)gr * HID + tx * 6);
#pragma unroll
        for (int p = 0; p < 3; ++p) {
            float lo, hi;
            unpack2(acc[r][p], lo, hi);
            int j = tx * 6 + p * 2;
            float flo = lo + g_bfold[j];
            float fhi = hi + g_bfold[j + 1];
            g_hw[(size_t)gr * HID + j]     = flo;
            g_hw[(size_t)gr * HID + j + 1] = fhi;
            hp[p] = __floats2half2_rn(dv * flo, dv * fhi);
        }
    }
}

// ---------------- stats (deterministic 2-level column mean/var) ----------------
__global__ void k_stats1(int sel, int N) {
    const float* __restrict__ Y = (sel == 0) ? g_y : (g_cat + 96);
    int ld = (sel == 0) ? HID : CAT;
    int col = threadIdx.x % 48, rs = threadIdx.x / 48;    // blockDim 384
    float s = 0.f, q = 0.f;
    for (int r = blockIdx.x * 8 + rs; r < N; r += 128 * 8) {
        float v = Y[(size_t)r * ld + col];
        s += v; q += v * v;
    }
    __shared__ float sh[384], shq[384];
    sh[threadIdx.x] = s; shq[threadIdx.x] = q;
    __syncthreads();
    if (threadIdx.x < 48) {
#pragma unroll
        for (int i = 1; i < 8; ++i) { s += sh[i * 48 + col]; q += shq[i * 48 + col]; }
        g_part[blockIdx.x * 96 + col] = s;
        g_part[blockIdx.x * 96 + 48 + col] = q;
    }
}

// fused: BN affine (scale/shift) + fold into next-layer weight
__global__ void k_bnfold(const float* __restrict__ g, const float* __restrict__ b,
                         const float* __restrict__ Wc, float invN) {
    int j = threadIdx.x;
    if (j < 48) {
        float s = 0.f, q = 0.f;
        for (int blk = 0; blk < 128; ++blk) { s += g_part[blk * 96 + j]; q += g_part[blk * 96 + 48 + j]; }
        float mean = s * invN;
        float var = q * invN - mean * mean;
        float a = g[j] * rsqrtf(var + EPSB);
        g_scale[j] = a;
        g_shift[j] = b[j] - mean * a;
    }
    __syncthreads();
    for (int idx = threadIdx.x; idx < HID * HID; idx += blockDim.x)
        g_wfold[idx] = g_scale[idx / HID] * Wc[idx];
    if (threadIdx.x < HID) {
        float s = 0.f;
        for (int k = 0; k < HID; ++k) s += g_shift[k] * Wc[k * HID + threadIdx.x];
        g_bfold[threadIdx.x] = s;
    }
}

__global__ void k_bnfold_out(const float* __restrict__ g, const float* __restrict__ b,
                             const float* __restrict__ Wout, const float* __restrict__ bout,
                             float invN) {
    int j = threadIdx.x;
    if (j < 48) {
        float s = 0.f, q = 0.f;
        for (int blk = 0; blk < 128; ++blk) { s += g_part[blk * 96 + j]; q += g_part[blk * 96 + 48 + j]; }
        float mean = s * invN;
        float var = q * invN - mean * mean;
        float a = g[j] * rsqrtf(var + EPSB);
        g_scale[j] = a;
        g_shift[j] = b[j] - mean * a;
    }
    __syncthreads();
    for (int idx = threadIdx.x; idx < CAT * NC; idx += blockDim.x) {
        int k = idx / NC;
        g_wout[idx] = (k < 96) ? Wout[idx] : g_scale[k - 96] * Wout[idx];
    }
    if (threadIdx.x < NC) {
        float s = bout[threadIdx.x];
        for (int k = 0; k < HID; ++k) s += g_shift[k] * Wout[(96 + k) * NC + threadIdx.x];
        g_bout[threadIdx.x] = s;
    }
}

// ---------------- sparse conv (gather, CSR by dst; fp16 neighbor table) ----------------
// out[dst] = lrelu( dinv[dst] * ( hws[dst] + Σ_e ew_e * hws[src] ) + bias )
__global__ void k_conv(const float* __restrict__ bias, int outSel, int N) {
    float* __restrict__ out = (outSel == 0) ? g_y : (g_cat + 96);
    int ld = (outSel == 0) ? HID : CAT;
    int g = blockIdx.x * blockDim.x + threadIdx.x;
    int node = g >> 2;
    if (node >= N) return;
    int sub = g & 3;                          // 12 floats each
    float di = g_dinv[node];
    // self term from fp32 table: hws_self = di * hw_self
    const float4* hs = (const float4*)(g_hw + (size_t)node * HID + sub * 12);
    float4 a0 = hs[0], a1 = hs[1], a2 = hs[2];
    float4 c0 = make_float4(di * a0.x, di * a0.y, di * a0.z, di * a0.w);
    float4 c1 = make_float4(di * a1.x, di * a1.y, di * a1.z, di * a1.w);
    float4 c2 = make_float4(di * a2.x, di * a2.y, di * a2.z, di * a2.w);
    int beg = g_rowptr[node], end = g_rowptr[node + 1];
#pragma unroll 2
    for (int j = beg; j < end; ++j) {
        float2 e = g_ec[j];
        int src = __float_as_int(e.y);
        float w = e.x;
        const uint2* p = (const uint2*)(g_hwh + (size_t)src * HID + sub * 12);
        uint2 u0 = p[0], u1 = p[1], u2 = p[2];
        float2 f0 = h2f(u0.x), f1 = h2f(u0.y);
        float2 f2 = h2f(u1.x), f3 = h2f(u1.y);
        float2 f4 = h2f(u2.x), f5 = h2f(u2.y);
        c0.x += w * f0.x; c0.y += w * f0.y; c0.z += w * f1.x; c0.w += w * f1.y;
        c1.x += w * f2.x; c1.y += w * f2.y; c1.z += w * f3.x; c1.w += w * f3.y;
        c2.x += w * f4.x; c2.y += w * f4.y; c2.z += w * f5.x; c2.w += w * f5.y;
    }
    int cb = sub * 12;
    const float4* bp = (const float4*)(bias + cb);
    float4 b0 = bp[0], b1 = bp[1], b2 = bp[2];
    float4 o0 = make_float4(lrelu(di * c0.x + b0.x), lrelu(di * c0.y + b0.y),
                            lrelu(di * c0.z + b0.z), lrelu(di * c0.w + b0.w));
    float4 o1 = make_float4(lrelu(di * c1.x + b1.x), lrelu(di * c1.y + b1.y),
                            lrelu(di * c1.z + b1.z), lrelu(di * c1.w + b1.w));
    float4 o2 = make_float4(lrelu(di * c2.x + b2.x), lrelu(di * c2.y + b2.y),
                            lrelu(di * c2.z + b2.z), lrelu(di * c2.w + b2.w));
    float4* op = (float4*)(out + (size_t)node * ld + cb);
    op[0] = o0; op[1] = o1; op[2] = o2;
}

// ---------------- head GEMM + log_softmax (f32x2) ----------------
__global__ __launch_bounds__(128) void k_gemm_out(float* __restrict__ out, int N) {
    __shared__ float As[128][49];
    __shared__ float Ws[48][40];
    int tid = threadIdx.x;
    int ty = tid >> 3, tx = tid & 7;          // 16 x 8; 8 rows x 5 cols per thread
    int base = blockIdx.x * 128;
    unsigned long long acc2[8][2];
    float acc1[8];
#pragma unroll
    for (int r = 0; r < 8; ++r) { acc2[r][0] = 0ull; acc2[r][1] = 0ull; acc1[r] = 0.f; }

#pragma unroll 1
    for (int k0 = 0; k0 < CAT; k0 += 48) {
#pragma unroll
        for (int t = 0; t < 12; ++t) {
            int idx = tid + t * 128;          // float4
            int r = idx / 12, q = idx % 12;
            float4 v = make_float4(0.f, 0.f, 0.f, 0.f);
            int gr = base + r;
            if (gr < N) v = *(const float4*)(g_cat + (size_t)gr * CAT + k0 + q * 4);
            int j = q * 4;
            As[r][j + 0] = v.x; As[r][j + 1] = v.y; As[r][j + 2] = v.z; As[r][j + 3] = v.w;
        }
#pragma unroll
        for (int t = 0; t < 15; ++t) {
            int idx = tid + t * 128;          // 0..1919
            Ws[idx / 40][idx % 40] = g_wout[k0 * 40 + idx];
        }
        __syncthreads();
#pragma unroll 8
        for (int kk = 0; kk < 48; ++kk) {
            float w0 = Ws[kk][tx * 5 + 0], w1 = Ws[kk][tx * 5 + 1];
            float w2 = Ws[kk][tx * 5 + 2], w3 = Ws[kk][tx * 5 + 3];
            float w4 = Ws[kk][tx * 5 + 4];
            unsigned long long wp0 = pack2(w0, w1), wp1 = pack2(w2, w3);
#pragma unroll
            for (int r = 0; r < 8; ++r) {
                float a = As[ty * 8 + r][kk];
                unsigned long long a2 = pack2(a, a);
                acc2[r][0] = fma2(a2, wp0, acc2[r][0]);
                acc2[r][1] = fma2(a2, wp1, acc2[r][1]);
                acc1[r] = fmaf(a, w4, acc1[r]);
            }
        }
        __syncthreads();
    }
#pragma unroll
    for (int r = 0; r < 8; ++r) {
        int gr = base + ty * 8 + r;
        float v[5];
        unpack2(acc2[r][0], v[0], v[1]);
        unpack2(acc2[r][1], v[2], v[3]);
        v[4] = acc1[r];
        float m = -1e30f;
#pragma unroll
        for (int c = 0; c < 5; ++c) { v[c] += g_bout[tx * 5 + c]; m = fmaxf(m, v[c]); }
#pragma unroll
        for (int off = 1; off < 8; off <<= 1) m = fmaxf(m, __shfl_xor_sync(0xffffffffu, m, off));
        float se = 0.f;
#pragma unroll
        for (int c = 0; c < 5; ++c) se += __expf(v[c] - m);
#pragma unroll
        for (int off = 1; off < 8; off <<= 1) se += __shfl_xor_sync(0xffffffffu, se, off);
        float ls = __logf(se);
        if (gr < N) {
#pragma unroll
            for (int c = 0; c < 5; ++c) out[(size_t)gr * NC + tx * 5 + c] = v[c] - m - ls;
        }
    }
}

// ---------------- launch ----------------
extern "C" void kernel_launch(void* const* d_in, const int* in_sizes, int n_in,
                              void* d_out, int out_size) {
    const float* x    = (const float*)d_in[0];
    const int*   ei   = (const int*)d_in[1];     // int32 (JAX demotes int64 without x64)
    const float* ew   = (const float*)d_in[2];
    const float* Wf   = (const float*)d_in[3];
    const float* bf   = (const float*)d_in[4];
    const float* bn1g = (const float*)d_in[5];
    const float* bn1b = (const float*)d_in[6];
    const float* Wc1  = (const float*)d_in[7];
    const float* bc1  = (const float*)d_in[8];
    const float* bn2g = (const float*)d_in[9];
    const float* bn2b = (const float*)d_in[10];
    const float* Wc2  = (const float*)d_in[11];
    const float* bc2  = (const float*)d_in[12];
    const float* bn3g = (const float*)d_in[13];
    const float* bn3b = (const float*)d_in[14];
    const float* Wout = (const float*)d_in[15];
    const float* bout = (const float*)d_in[16];
    float* out = (float*)d_out;

    int N = in_sizes[0] / FIN;
    int E = in_sizes[2];
    float invN = 1.0f / (float)N;
    int SB = (N + 1023) / 1024;
    int gE = (E + 255) / 256;
    int gT = (N + 127) / 128;       // gemm row blocks
    int gC = (4 * N + 255) / 256;   // conv

    // One-time host resources (streams/events/symbol addrs); identical work each call.
    static cudaStream_t s2 = nullptr;
    static cudaEvent_t evFork = nullptr, evDinv = nullptr, evJoin = nullptr;
    static void* degPtr = nullptr;
    static void* cntPtr = nullptr;
    if (s2 == nullptr) {
        cudaStreamCreateWithFlags(&s2, cudaStreamNonBlocking);
        cudaEventCreateWithFlags(&evFork, cudaEventDisableTiming);
        cudaEventCreateWithFlags(&evDinv, cudaEventDisableTiming);
        cudaEventCreateWithFlags(&evJoin, cudaEventDisableTiming);
        cudaGetSymbolAddress(&degPtr, g_deg);
        cudaGetSymbolAddress(&cntPtr, g_cnt);
    }

    // ---- fork: edge pipeline on s2, node pipeline on default stream ----
    cudaEventRecord(evFork, 0);
    cudaStreamWaitEvent(s2, evFork, 0);

    cudaMemsetAsync(degPtr, 0, (size_t)N * sizeof(float), s2);
    cudaMemsetAsync(cntPtr, 0, (size_t)N * sizeof(int), s2);
    k_degcnt<<<gE, 256, 0, s2>>>(ei, ew, E);
    k_scanA<<<SB, 1024, 0, s2>>>(N);
    cudaEventRecord(evDinv, s2);                 // dinv ready (needed by gemm_h)
    k_scanC<<<SB, 1024, 0, s2>>>(SB, N);
    k_fill<<<gE, 256, 0, s2>>>(ei, ew, E);
    cudaEventRecord(evJoin, s2);                 // CSR ready (needed by conv)

    // node pipeline
    k_gemm1<<<gT, 128>>>(x, Wf, bf, N);
    k_stats1<<<128, 384>>>(0, N);
    k_bnfold<<<1, 256>>>(bn1g, bn1b, Wc1, invN);
    cudaStreamWaitEvent(0, evDinv, 0);
    k_gemm_h<<<gT, 128>>>(0, N);

    cudaStreamWaitEvent(0, evJoin, 0);
    k_conv<<<gC, 256>>>(bc1, 0, N);

    k_stats1<<<128, 384>>>(0, N);
    k_bnfold<<<1, 256>>>(bn2g, bn2b, Wc2, invN);
    k_gemm_h<<<gT, 128>>>(HID, N);
    k_conv<<<gC, 256>>>(bc2, 1, N);

    k_stats1<<<128, 384>>>(1, N);
    k_bnfold_out<<<1, 256>>>(bn3g, bn3b, Wout, bout, invN);

    k_gemm_out<<<gT, 128>>>(out, N);
}